// round 15
// baseline (speedup 1.0000x reference)
#include <cuda_runtime.h>
#include <cuda_fp16.h>
#include <math.h>

// B=4, C=2, H=W=1024, DS=4 -> 256x256, NUM_SEEDS=32, 15 steps, pool 7x7.
// Packed flood: half2 = (chA, chB) in crop coords. 64 pairs x 2 CTAs (rows 0-57 / 39-96).
#define NCH   128
#define NROWS 58
#define PH2   116            // half2 words per row (464B; 116%32=20 -> conflict-free LDS.128)
#define PADC2 4              // col c at half2 index PADC2 + c (left pad 4; capacity cols -4..111)
#define AW    (NROWS * PH2)  // words per array
#define SMEM_BYTES (3 * AW * 4)

__device__ __half   g_road[4 * 256 * 256];
__device__ unsigned g_gtb[4 * 256 * 8];
__device__ int      g_sr[NCH];
__device__ int      g_sc[NCH];
__device__ int      g_scnt[NCH];
__device__ float    g_sv[NCH];
__device__ float    g_partialC[NCH];     // per-CTA partial
__device__ uint4    g_halo[64][2][9][26];
__device__ unsigned g_flag[NCH];         // reset to 0 by finalize each launch
__device__ int      g_done;

__global__ void k_prep(const float* __restrict__ cls, const int* __restrict__ lab,
                       const float4* __restrict__ seeds) {
    if (blockIdx.x < 1024) {
        int idx = blockIdx.x * 256 + threadIdx.x;
        int j = idx & 255, i = (idx >> 8) & 255, b = idx >> 16;
        const float* c0 = cls + (size_t)(b * 2 + 0) * 1048576;
        const float* c1 = cls + (size_t)(b * 2 + 1) * 1048576;
        int r1 = 4 * i + 1, r2 = 4 * i + 2, cc = 4 * j;
        float4 a0 = *(const float4*)(c0 + r1 * 1024 + cc);
        float4 a1 = *(const float4*)(c1 + r1 * 1024 + cc);
        float4 b0 = *(const float4*)(c0 + r2 * 1024 + cc);
        float4 b1 = *(const float4*)(c1 + r2 * 1024 + cc);
        float p1 = 1.f / (1.f + expf(a0.y - a1.y));
        float p2 = 1.f / (1.f + expf(a0.z - a1.z));
        float p3 = 1.f / (1.f + expf(b0.y - b1.y));
        float p4 = 1.f / (1.f + expf(b0.z - b1.z));
        g_road[idx] = __float2half(0.25f * (p1 + p2 + p3 + p4));
        int g = lab[((size_t)b * 1024 + 4 * i) * 1024 + 4 * j];
        unsigned bits = __ballot_sync(0xffffffffu, g != 0);
        if ((threadIdx.x & 31) == 0)
            g_gtb[((size_t)b * 256 + i) * 8 + (j >> 5)] = bits;
    }
    {
        const unsigned n4 = (4 * 32 * 256 * 256) / 4;
        for (unsigned i = blockIdx.x * 256u + threadIdx.x; i < n4; i += 2048u * 256u) {
            float4 v = seeds[i];
            if (v.x > 0.f || v.y > 0.f || v.z > 0.f || v.w > 0.f) {
                float vals[4] = {v.x, v.y, v.z, v.w};
                #pragma unroll
                for (int k = 0; k < 4; k++) if (vals[k] > 0.f) {
                    unsigned idx = i * 4u + k;
                    int ch = idx >> 16;
                    g_sr[ch] = (idx >> 8) & 255;
                    g_sc[ch] = idx & 255;
                    g_sv[ch] = vals[k];
                    g_scnt[ch] = 1;
                }
            }
        }
    }
    asm volatile("griddepcontrol.launch_dependents;" ::: "memory");
}

__device__ __forceinline__ unsigned getword(const unsigned* row, int start) {
    int w = start >> 5;
    int sh = start & 31;
    unsigned lo = ((unsigned)w < 8u) ? row[w] : 0u;
    unsigned hi = ((unsigned)(w + 1) < 8u) ? row[w + 1] : 0u;
    return __funnelshift_r(lo, hi, sh);
}
__device__ __forceinline__ uint4 bshl(uint4 v, int s) {
    return make_uint4(v.x << s, __funnelshift_l(v.x, v.y, s),
                      __funnelshift_l(v.y, v.z, s), __funnelshift_l(v.z, v.w, s));
}
__device__ __forceinline__ uint4 bshr(uint4 v, int s) {
    return make_uint4(__funnelshift_r(v.x, v.y, s), __funnelshift_r(v.y, v.z, s),
                      __funnelshift_r(v.z, v.w, s), v.w >> s);
}
__device__ __forceinline__ uint4 bor(uint4 a, uint4 b) {
    return make_uint4(a.x | b.x, a.y | b.y, a.z | b.z, a.w | b.w);
}
__device__ __forceinline__ unsigned hmax2u(unsigned a, unsigned b) {
    __half2 r = __hmax2(*(__half2*)&a, *(__half2*)&b);
    return *(unsigned*)&r;
}
__device__ __forceinline__ unsigned hmin2u(unsigned a, unsigned b) {
    __half2 r = __hmin2(*(__half2*)&a, *(__half2*)&b);
    return *(unsigned*)&r;
}
__device__ __forceinline__ uint4 h8max(uint4 a, uint4 b) {
    return make_uint4(hmax2u(a.x, b.x), hmax2u(a.y, b.y),
                      hmax2u(a.z, b.z), hmax2u(a.w, b.w));
}
__device__ __forceinline__ uint4 h8min(uint4 a, uint4 b) {
    return make_uint4(hmin2u(a.x, b.x), hmin2u(a.y, b.y),
                      hmin2u(a.z, b.z), hmin2u(a.w, b.w));
}
__device__ __forceinline__ int imax(int a, int b) { return a > b ? a : b; }
__device__ __forceinline__ int imin(int a, int b) { return a < b ? a : b; }

// ctaid = 2*pair + half. half0: crop rows 0..57; half1: 39..96. lr = gr - 39*half.
__global__ void __launch_bounds__(1024, 1) k_flood(float* __restrict__ out) {
    extern __shared__ unsigned smw[];
    unsigned* Asm  = smw;            // packed state
    unsigned* Btsm = smw + AW;       // h-pass temp
    unsigned* Msm  = smw + 2 * AW;   // packed mask
    __shared__ uint4 GsA[97], GhA[97], GmA[97];
    __shared__ uint4 GsB[97], GhB[97], GmB[97];
    __shared__ float wpart[32];
    __shared__ int   s_last;

    unsigned tid = threadIdx.x;
    int ctaid = blockIdx.x;
    int half = ctaid & 1, pair = ctaid >> 1;
    int rowbase = 39 * half;
    int chA = 2 * pair, chB = 2 * pair + 1;
    const float c0log = -logf(1.0f - 1e-7f);

    // ---- pre-dependency: zero A and M ----
    {
        uint4 z = make_uint4(0, 0, 0, 0);
        uint4* A4 = (uint4*)Asm;
        uint4* M4 = (uint4*)Msm;
        for (int i = tid; i < AW / 4; i += 1024) { A4[i] = z; M4[i] = z; }
    }
    asm volatile("griddepcontrol.wait;" ::: "memory");
    __syncthreads();

    bool sA = (g_scnt[chA] != 0), sB = (g_scnt[chB] != 0);
    int grA = g_sr[chA] - 48, gcA = g_sc[chA] - 48;
    int grB = g_sr[chB] - 48, gcB = g_sc[chB] - 48;
    int bA = chA >> 5, bB = chB >> 5;   // same batch actually (chB = chA+1, >>5 equal unless boundary; compute separately)
    float svA = g_sv[chA], svB = g_sv[chB];
    __half hA = sA ? __float2half(svA) : __ushort_as_half((unsigned short)0);
    __half hB = sB ? __float2half(svB) : __ushort_as_half((unsigned short)0);
    unsigned seedpack = (unsigned)__half_as_ushort(hA) | ((unsigned)__half_as_ushort(hB) << 16);

    // ---- stage packed mask M (rows rowbase..rowbase+57, cols 0..96) ----
    for (unsigned u = tid; u < (unsigned)NROWS * 97u; u += 1024) {
        unsigned lr = u / 97u;
        unsigned x = u - lr * 97u;
        int cr = (int)lr + rowbase;
        unsigned short ma = 0, mb = 0;
        {
            int gy = grA + cr, gx = gcA + (int)x;
            if (sA && (unsigned)gy < 256u && (unsigned)gx < 256u)
                ma = __half_as_ushort(g_road[(bA << 16) + (gy << 8) + gx]);
        }
        {
            int gy = grB + cr, gx = gcB + (int)x;
            if (sB && (unsigned)gy < 256u && (unsigned)gx < 256u)
                mb = __half_as_ushort(g_road[(bB << 16) + (gy << 8) + gx]);
        }
        Msm[lr * PH2 + PADC2 + x] = (unsigned)ma | ((unsigned)mb << 16);
    }
    // ---- stage gt masks (full field, both channels, tids 830..1023) ----
    int id2 = (int)tid - 830;
    if (id2 >= 0) {
        int isA = (id2 < 97);
        int row = isA ? id2 : id2 - 97;
        if (row < 97) {
            int gr0 = isA ? grA : grB, gc0 = isA ? gcA : gcB;
            int bb = isA ? bA : bB;
            uint4 gm = make_uint4(0, 0, 0, 0);
            int gy = gr0 + row;
            if ((unsigned)gy < 256u) {
                const unsigned* rw = &g_gtb[((size_t)bb * 256 + gy) * 8];
                gm.x = getword(rw, gc0);
                gm.y = getword(rw, gc0 + 32);
                gm.z = getword(rw, gc0 + 64);
                gm.w = getword(rw, gc0 + 96) & 1u;
            }
            if (isA) { GmA[row] = gm; GsA[row] = make_uint4(0, 0, 0, 0); }
            else     { GmB[row] = gm; GsB[row] = make_uint4(0, 0, 0, 0); }
        }
    }
    __syncthreads();
    if (tid == 0) {
        Asm[(48 - rowbase) * PH2 + PADC2 + 48] = seedpack;
        if (sA) GsA[48].y |= (1u << 16);
        if (sB) GsB[48].y |= (1u << 16);
    }
    __syncthreads();

    #pragma unroll 1
    for (int it = 0; it < 15; it++) {
        int k = it % 3;
        // ---- exchange every 3 iterations (it = 3,6,9,12) ----
        if (k == 0 && it > 0) {
            int xk = it / 3;
            // write own boundary strip (9 rows x 26 uint4)
            if (tid < 234) {
                int r = tid / 26, q = tid - r * 26;
                int lrw = half ? (10 + r) : (39 + r);
                g_halo[pair][half][r][q] =
                    *(const uint4*)(Asm + lrw * PH2 + PADC2 + 4 * q);
            }
            __threadfence();
            __syncthreads();
            if (tid == 0) {
                atomicAdd(&g_flag[ctaid], 1u);
                while (*(volatile unsigned*)&g_flag[ctaid ^ 1] < (unsigned)xk) { }
                __threadfence();
            }
            __syncthreads();
            if (tid < 234) {
                int r = tid / 26, q = tid - r * 26;
                int lrr = half ? r : (49 + r);
                *(uint4*)(Asm + lrr * PH2 + PADC2 + 4 * q) =
                    g_halo[pair][half ^ 1][r][q];
            }
            __syncthreads();
        }

        int R = 3 * (it + 1);
        int lo = 48 - R, hi = 48 + R;
        int hlo = half ? 39 + 3 * k : 0;
        int hhi = half ? 96 : 57 - 3 * k;
        int tlo = half ? 42 + 3 * k : 0;
        int thi = half ? 96 : 54 - 3 * k;
        int Hlo = imax(lo - 3, hlo), Hhi = imin(hi + 3, hhi);
        int Tlo = imax(lo, tlo),     Thi = imin(hi, thi);
        int jlo = lo >> 2, jhi = hi >> 2;
        int needlo = 4 * jlo, needhi = 4 * jhi + 3;

        // ---- horizontal 7-max (packed): A -> Bt ----
        {
            unsigned g = tid / 58u;
            int y = Hlo + (int)(tid - g * 58u);
            int X = (int)(g << 3);
            if (g < 13u && y <= Hhi && X + 7 >= needlo && X <= needhi) {
                int lr = y - rowbase;
                const uint4* src = (const uint4*)(Asm + lr * PH2 + X);  // cols X-4..X+11
                uint4 t0 = src[0], t1 = src[1], t2 = src[2], t3 = src[3];
                unsigned v[16] = {t0.x, t0.y, t0.z, t0.w, t1.x, t1.y, t1.z, t1.w,
                                  t2.x, t2.y, t2.z, t2.w, t3.x, t3.y, t3.z, t3.w};
                unsigned p2[15];
                #pragma unroll
                for (int i = 0; i < 15; i++) p2[i] = hmax2u(v[i], v[i + 1]);
                unsigned p4[13];
                #pragma unroll
                for (int i = 0; i < 13; i++) p4[i] = hmax2u(p2[i], p2[i + 2]);
                unsigned o[8];
                #pragma unroll
                for (int c = 0; c < 8; c++) o[c] = hmax2u(p4[c + 1], p4[c + 4]);
                uint4* dst = (uint4*)(Btsm + lr * PH2 + PADC2 + X);
                dst[0] = make_uint4(o[0], o[1], o[2], o[3]);
                dst[1] = make_uint4(o[4], o[5], o[6], o[7]);
            }
        }
        // ---- gt horizontal dilate (both channels) ----
        if (id2 >= 0) {
            int isA = (id2 < 97);
            int row = isA ? id2 : id2 - 97;
            uint4 x = isA ? GsA[row] : GsB[row];
            uint4 d = bor(x, bor(bshl(x, 1), bshr(x, 1)));
            d = bor(d, bor(bshl(x, 2), bshr(x, 2)));
            d = bor(d, bor(bshl(x, 3), bshr(x, 3)));
            if (isA) GhA[row] = d; else GhB[row] = d;
        }
        __syncthreads();

        // ---- vertical 7-max (packed, 3-row bands, 4-col groups) + min(M) + seed ----
        {
            unsigned j = tid % 25u;
            unsigned band = tid / 25u;
            int y0 = Tlo + 3 * (int)band;
            if ((int)j >= jlo && (int)j <= jhi && y0 <= Thi) {
                unsigned coff = PADC2 + (j << 2);
                int c1 = imin(y0 + 1, Hhi), c2 = imin(y0 + 2, Hhi), c3 = imin(y0 + 3, Hhi);
                int c4 = imin(y0 + 4, Hhi), c5 = imin(y0 + 5, Hhi);
                #define BTROW(gy) (*(const uint4*)(Btsm + ((gy) - rowbase) * PH2 + coff))
                uint4 t = BTROW(y0 - 1);
                t = h8max(t, BTROW(y0));
                t = h8max(t, BTROW(c1));
                t = h8max(t, BTROW(c2));
                t = h8max(t, BTROW(c3));
                uint4 rA = BTROW(y0 - 3), rB = BTROW(y0 - 2);
                uint4 rC = BTROW(c4), rD = BTROW(c5);
                #undef BTROW
                uint4 m0 = h8max(t, h8max(rA, rB));
                uint4 m1 = h8max(t, h8max(rB, rC));
                uint4 m2 = h8max(t, h8max(rC, rD));
                int lr0 = y0 - rowbase;
                uint4 val0 = h8min(m0, *(const uint4*)(Msm + lr0 * PH2 + coff));
                if (y0 == 48 && j == 12u) val0.x = hmax2u(val0.x, seedpack);
                *(uint4*)(Asm + lr0 * PH2 + coff) = val0;
                if (y0 + 1 <= Thi) {
                    uint4 val1 = h8min(m1, *(const uint4*)(Msm + (lr0 + 1) * PH2 + coff));
                    if (y0 + 1 == 48 && j == 12u) val1.x = hmax2u(val1.x, seedpack);
                    *(uint4*)(Asm + (lr0 + 1) * PH2 + coff) = val1;
                }
                if (y0 + 2 <= Thi) {
                    uint4 val2 = h8min(m2, *(const uint4*)(Msm + (lr0 + 2) * PH2 + coff));
                    if (y0 + 2 == 48 && j == 12u) val2.x = hmax2u(val2.x, seedpack);
                    *(uint4*)(Asm + (lr0 + 2) * PH2 + coff) = val2;
                }
            }
        }
        // ---- gt vertical dilate + AND mask + seed ----
        if (id2 >= 0) {
            int isA = (id2 < 97);
            int row = isA ? id2 : id2 - 97;
            int ym3 = row - 3 < 0 ? 0 : row - 3;
            int yp3 = row + 3 > 96 ? 96 : row + 3;
            uint4 acc = isA ? GhA[ym3] : GhB[ym3];
            for (int yy = ym3 + 1; yy <= yp3; yy++)
                acc = bor(acc, isA ? GhA[yy] : GhB[yy]);
            uint4 gm = isA ? GmA[row] : GmB[row];
            acc.x &= gm.x; acc.y &= gm.y; acc.z &= gm.z; acc.w &= gm.w;
            if (row == 48 && (isA ? sA : sB)) acc.y |= (1u << 16);
            if (isA) GsA[row] = acc; else GsB[row] = acc;
        }
        __syncthreads();
    }

    // ---- BCE: rows cr<=47 -> half0, cr>=48 -> half1; unpack both channels ----
    int yloA = imax(3, -grA), yhiA = imin(93, 255 - grA);
    int xloA = imax(3, -gcA), xhiA = imin(93, 255 - gcA);
    int yloB = imax(3, -grB), yhiB = imin(93, 255 - grB);
    int xloB = imax(3, -gcB), xhiB = imin(93, 255 - gcB);
    float pm = 1.0f;
    int   pe = 0;
    for (unsigned u = tid; u < (unsigned)NROWS * 26u; u += 1024) {
        unsigned lr = u / 26u;
        unsigned q = u - lr * 26u;
        int cr = (int)lr + rowbase;
        if (half == 0 ? (cr > 47) : (cr < 48)) continue;
        uint4 pv = *(const uint4*)(Asm + lr * PH2 + PADC2 + (q << 2));
        unsigned pw[4] = {pv.x, pv.y, pv.z, pv.w};
        if (sA && cr >= yloA && cr <= yhiA) {
            uint4 gw = GsA[cr];
            #pragma unroll
            for (int e = 0; e < 4; e++) {
                int c = (int)(q << 2) + e;
                if (c >= xloA && c <= xhiA) {
                    float p = __half2float(__ushort_as_half((unsigned short)(pw[e] & 0xFFFFu)));
                    p = fminf(fmaxf(p, 1e-7f), 1.0f - 1e-7f);
                    int ws = c >> 5;
                    unsigned word = ws == 0 ? gw.x : ws == 1 ? gw.y : ws == 2 ? gw.z : gw.w;
                    pm *= ((word >> (c & 31)) & 1u) ? p : (1.0f - p);
                }
            }
            int bi = __float_as_int(pm);
            pe += (bi >> 23) - 127;
            pm = __int_as_float((bi & 0x007fffff) | 0x3f800000);
        }
        if (sB && cr >= yloB && cr <= yhiB) {
            uint4 gw = GsB[cr];
            #pragma unroll
            for (int e = 0; e < 4; e++) {
                int c = (int)(q << 2) + e;
                if (c >= xloB && c <= xhiB) {
                    float p = __half2float(__ushort_as_half((unsigned short)(pw[e] >> 16)));
                    p = fminf(fmaxf(p, 1e-7f), 1.0f - 1e-7f);
                    int ws = c >> 5;
                    unsigned word = ws == 0 ? gw.x : ws == 1 ? gw.y : ws == 2 ? gw.z : gw.w;
                    pm *= ((word >> (c & 31)) & 1u) ? p : (1.0f - p);
                }
            }
            int bi = __float_as_int(pm);
            pe += (bi >> 23) - 127;
            pm = __int_as_float((bi & 0x007fffff) | 0x3f800000);
        }
    }
    float local = -(__logf(pm) + (float)pe * 0.69314718056f);
    #pragma unroll
    for (int off = 16; off; off >>= 1)
        local += __shfl_down_sync(0xffffffffu, local, off);
    if ((tid & 31) == 0) wpart[tid >> 5] = local;
    __syncthreads();
    if (tid == 0) {
        float s = 0.f;
        #pragma unroll
        for (int kk = 0; kk < 32; kk++) s += wpart[kk];
        if (half == 0) {   // constants once per channel
            if (sA) s += (65536.0f - (float)((yhiA - yloA + 1) * (xhiA - xloA + 1))) * c0log;
            else    s += 65536.0f * c0log;
            if (sB) s += (65536.0f - (float)((yhiB - yloB + 1) * (xhiB - xloB + 1))) * c0log;
            else    s += 65536.0f * c0log;
        }
        g_partialC[ctaid] = s;
    }

    // ---- last-block finalize ----
    if (tid == 0) {
        __threadfence();
        int old = atomicAdd(&g_done, 1);
        s_last = (old == NCH - 1);
    }
    __syncthreads();
    if (s_last && tid < 32) {
        float fv = g_partialC[tid] + g_partialC[tid + 32] +
                   g_partialC[tid + 64] + g_partialC[tid + 96];
        #pragma unroll
        for (int off = 16; off; off >>= 1)
            fv += __shfl_down_sync(0xffffffffu, fv, off);
        g_flag[tid] = 0; g_flag[tid + 32] = 0; g_flag[tid + 64] = 0; g_flag[tid + 96] = 0;
        if (tid == 0) {
            out[0] = 0.5f * fv / 8388608.0f;
            g_done = 0;
        }
    }
}

extern "C" void kernel_launch(void* const* d_in, const int* in_sizes, int n_in,
                              void* d_out, int out_size) {
    const float* cls = (const float*)d_in[0];
    const int* lab   = (const int*)d_in[1];
    const float4* seeds = (const float4*)d_in[2];

    cudaFuncSetAttribute(k_flood, cudaFuncAttributeMaxDynamicSharedMemorySize, SMEM_BYTES);

    k_prep<<<2048, 256>>>(cls, lab, seeds);

    cudaLaunchConfig_t cfg = {};
    cfg.gridDim = dim3(128, 1, 1);
    cfg.blockDim = dim3(1024, 1, 1);
    cfg.dynamicSmemBytes = SMEM_BYTES;
    cfg.stream = 0;
    cudaLaunchAttribute attr[1];
    attr[0].id = cudaLaunchAttributeProgrammaticStreamSerialization;
    attr[0].val.programmaticStreamSerializationAllowed = 1;
    cfg.attrs = attr;
    cfg.numAttrs = 1;
    float* outp = (float*)d_out;
    cudaError_t e = cudaLaunchKernelEx(&cfg, k_flood, outp);
    if (e != cudaSuccess) {
        k_flood<<<128, 1024, SMEM_BYTES>>>(outp);
    }
}

// round 16
// speedup vs baseline: 1.4545x; 1.4545x over previous
#include <cuda_runtime.h>
#include <cuda_fp16.h>
#include <math.h>

// B=4, C=2, H=W=1024, DS=4 -> 256x256, NUM_SEEDS=32, 15 steps, pool 7x7.
#define NCH   128
#define RS    97
#define PH    136             // halfs per row (272B) -> conflict-free LDS.128
#define PADC  8
#define ARRH  (RS * PH + 16)
#define SMEM_BYTES (3 * ARRH * 2)

__device__ float    g_road[4 * 256 * 256];
__device__ unsigned g_gtb[4 * 256 * 8];
__device__ int   g_sr[NCH];
__device__ int   g_sc[NCH];
__device__ int   g_scnt[NCH];
__device__ float g_sv[NCH];
__device__ float g_partial[NCH];
__device__ int   g_done;

__global__ void k_prep(const float* __restrict__ cls, const int* __restrict__ lab,
                       const float4* __restrict__ seeds) {
    if (blockIdx.x < 1024) {
        int idx = blockIdx.x * 256 + threadIdx.x;
        int j = idx & 255, i = (idx >> 8) & 255, b = idx >> 16;
        const float* c0 = cls + (size_t)(b * 2 + 0) * 1048576;
        const float* c1 = cls + (size_t)(b * 2 + 1) * 1048576;
        int r1 = 4 * i + 1, r2 = 4 * i + 2, cc = 4 * j;
        float4 a0 = *(const float4*)(c0 + r1 * 1024 + cc);
        float4 a1 = *(const float4*)(c1 + r1 * 1024 + cc);
        float4 b0 = *(const float4*)(c0 + r2 * 1024 + cc);
        float4 b1 = *(const float4*)(c1 + r2 * 1024 + cc);
        float p1 = 1.f / (1.f + expf(a0.y - a1.y));
        float p2 = 1.f / (1.f + expf(a0.z - a1.z));
        float p3 = 1.f / (1.f + expf(b0.y - b1.y));
        float p4 = 1.f / (1.f + expf(b0.z - b1.z));
        g_road[idx] = 0.25f * (p1 + p2 + p3 + p4);
        int g = lab[((size_t)b * 1024 + 4 * i) * 1024 + 4 * j];
        unsigned bits = __ballot_sync(0xffffffffu, g != 0);
        if ((threadIdx.x & 31) == 0)
            g_gtb[((size_t)b * 256 + i) * 8 + (j >> 5)] = bits;
    }
    {
        const unsigned n4 = (4 * 32 * 256 * 256) / 4;
        for (unsigned i = blockIdx.x * 256u + threadIdx.x; i < n4; i += 2048u * 256u) {
            float4 v = seeds[i];
            if (v.x > 0.f || v.y > 0.f || v.z > 0.f || v.w > 0.f) {
                float vals[4] = {v.x, v.y, v.z, v.w};
                #pragma unroll
                for (int k = 0; k < 4; k++) if (vals[k] > 0.f) {
                    unsigned idx = i * 4u + k;
                    int ch = idx >> 16;
                    g_sr[ch] = (idx >> 8) & 255;
                    g_sc[ch] = idx & 255;
                    g_sv[ch] = vals[k];
                    g_scnt[ch] = 1;
                }
            }
        }
    }
    asm volatile("griddepcontrol.launch_dependents;" ::: "memory");
}

__device__ __forceinline__ unsigned getword(const unsigned* row, int start) {
    int w = start >> 5;
    int sh = start & 31;
    unsigned lo = ((unsigned)w < 8u) ? row[w] : 0u;
    unsigned hi = ((unsigned)(w + 1) < 8u) ? row[w + 1] : 0u;
    return __funnelshift_r(lo, hi, sh);
}
__device__ __forceinline__ uint4 bshl(uint4 v, int s) {
    return make_uint4(v.x << s, __funnelshift_l(v.x, v.y, s),
                      __funnelshift_l(v.y, v.z, s), __funnelshift_l(v.z, v.w, s));
}
__device__ __forceinline__ uint4 bshr(uint4 v, int s) {
    return make_uint4(__funnelshift_r(v.x, v.y, s), __funnelshift_r(v.y, v.z, s),
                      __funnelshift_r(v.z, v.w, s), v.w >> s);
}
__device__ __forceinline__ uint4 bor(uint4 a, uint4 b) {
    return make_uint4(a.x | b.x, a.y | b.y, a.z | b.z, a.w | b.w);
}
__device__ __forceinline__ unsigned hmax2u(unsigned a, unsigned b) {
    __half2 r = __hmax2(*(__half2*)&a, *(__half2*)&b);
    return *(unsigned*)&r;
}
__device__ __forceinline__ unsigned hmin2u(unsigned a, unsigned b) {
    __half2 r = __hmin2(*(__half2*)&a, *(__half2*)&b);
    return *(unsigned*)&r;
}
__device__ __forceinline__ uint4 h8max(uint4 a, uint4 b) {
    return make_uint4(hmax2u(a.x, b.x), hmax2u(a.y, b.y),
                      hmax2u(a.z, b.z), hmax2u(a.w, b.w));
}
__device__ __forceinline__ uint4 h8min(uint4 a, uint4 b) {
    return make_uint4(hmin2u(a.x, b.x), hmin2u(a.y, b.y),
                      hmin2u(a.z, b.z), hmin2u(a.w, b.w));
}
#define FSR(a, b) __funnelshift_r((a), (b), 16)

// One channel per CTA, 1024 threads, 128 CTAs (full chip).
__global__ void __launch_bounds__(1024, 1) k_flood(float* __restrict__ out) {
    extern __shared__ __half smh[];
    __half* A  = smh;
    __half* Bt = smh + ARRH;
    __half* M  = smh + 2 * ARRH;
    __shared__ uint4 Gs[RS];
    __shared__ uint4 Gh[RS];
    __shared__ uint4 Gm[RS];
    __shared__ float wpart[32];
    __shared__ int   s_last;

    unsigned tid = threadIdx.x;
    int ch  = blockIdx.x;
    int b   = ch >> 5;
    const float c0log = -logf(1.0f - 1e-7f);

    // ---- pre-dependency: zero A and M while k_prep finishes (PDL overlap) ----
    {
        uint4 z = make_uint4(0, 0, 0, 0);
        uint4* A8 = (uint4*)A;
        uint4* M8 = (uint4*)M;
        for (int i = tid; i < ARRH / 8; i += 1024) { A8[i] = z; M8[i] = z; }
    }
    asm volatile("griddepcontrol.wait;" ::: "memory");
    __syncthreads();

    bool hasseed = (g_scnt[ch] != 0);
    if (!hasseed) {
        if (tid == 0) g_partial[ch] = 65536.0f * c0log;
    } else {
        int sr = g_sr[ch], sc = g_sc[ch];
        float sv = g_sv[ch];
        int gr0 = sr - 48, gc0 = sc - 48;

        if (tid >= 927) {
            int gy2 = tid - 927;               // 0..96
            int gy = gr0 + gy2;
            uint4 gm = make_uint4(0, 0, 0, 0);
            if ((unsigned)gy < 256u) {
                const unsigned* row = &g_gtb[((size_t)b * 256 + gy) * 8];
                gm.x = getword(row, gc0);
                gm.y = getword(row, gc0 + 32);
                gm.z = getword(row, gc0 + 64);
                gm.w = getword(row, gc0 + 96);
            }
            gm.w &= 1u;
            Gm[gy2] = gm;
            Gs[gy2] = make_uint4(0, 0, 0, 0);
        }
        for (unsigned idx = tid; idx < RS * RS; idx += 1024) {
            unsigned y = idx / RS;
            unsigned x = idx - y * RS;
            int gy = gr0 + (int)y, gx = gc0 + (int)x;
            float m = 0.f;
            if ((unsigned)gy < 256u && (unsigned)gx < 256u)
                m = g_road[(b << 16) + (gy << 8) + gx];
            M[y * PH + PADC + x] = __float2half(m);
        }
        __syncthreads();

        unsigned seedlo = (unsigned)__half_as_ushort(__float2half(sv));
        int w = tid >> 5, l = tid & 31;

        // ======== warp-local fast path: iterations 0..3 (radius <= 12) ========
        if (w == 0) {
            // float field: lane = row 33+l, regs = cols 32..63 (16 half2)
            int rr = 33 + l;
            const unsigned* mrow = (const unsigned*)(M + rr * PH + PADC + 32);
            unsigned v[16];
            #pragma unroll
            for (int k = 0; k < 16; k++) v[k] = 0u;
            if (l == 15) v[8] = seedlo;          // row 48, col 48 (lo half)
            #pragma unroll
            for (int it2 = 0; it2 < 4; it2++) {
                unsigned a[17], bb[16], h[14];
                a[16] = 0u;
                #pragma unroll
                for (int k = 0; k < 16; k++) {
                    unsigned nx = (k + 1 < 16) ? v[k + 1] : 0u;
                    a[k] = hmax2u(v[k], FSR(v[k], nx));
                }
                #pragma unroll
                for (int k = 0; k < 16; k++)
                    bb[k] = hmax2u(a[k], a[k + 1]);
                #pragma unroll
                for (int k = 0; k < 14; k++)
                    h[k] = hmax2u(FSR(bb[k], bb[k + 1]), bb[k + 2]);
                #pragma unroll
                for (int k = 0; k < 14; k++) {
                    unsigned p  = hmax2u(h[k], __shfl_down_sync(0xffffffffu, h[k], 1));
                    unsigned b4 = hmax2u(p,   __shfl_down_sync(0xffffffffu, p, 2));
                    unsigned o  = hmax2u(b4,  __shfl_up_sync(0xffffffffu, b4, 3));
                    v[k + 2] = hmin2u(o, mrow[k + 2]);
                }
                if (l == 15) v[8] = hmax2u(v[8], seedlo);
            }
            uint4* dst = (uint4*)(A + rr * PH + PADC + 32);
            dst[0] = make_uint4(v[0],  v[1],  v[2],  v[3]);
            dst[1] = make_uint4(v[4],  v[5],  v[6],  v[7]);
            dst[2] = make_uint4(v[8],  v[9],  v[10], v[11]);
            dst[3] = make_uint4(v[12], v[13], v[14], v[15]);
        } else if (w == 1) {
            // gt bit field: lane = row 33+l, full-row uint4
            int rr = 33 + l;
            uint4 gm = Gm[rr];
            uint4 grow = make_uint4(0, 0, 0, 0);
            if (l == 15) grow.y |= (1u << 16);
            #pragma unroll
            for (int it2 = 0; it2 < 4; it2++) {
                uint4 gh = bor(grow, bor(bshl(grow, 1), bshr(grow, 1)));
                gh = bor(gh, bor(bshl(grow, 2), bshr(grow, 2)));
                gh = bor(gh, bor(bshl(grow, 3), bshr(grow, 3)));
                uint4 p, b4, o;
                p.x = gh.x | __shfl_down_sync(0xffffffffu, gh.x, 1);
                p.y = gh.y | __shfl_down_sync(0xffffffffu, gh.y, 1);
                p.z = gh.z | __shfl_down_sync(0xffffffffu, gh.z, 1);
                p.w = gh.w | __shfl_down_sync(0xffffffffu, gh.w, 1);
                b4.x = p.x | __shfl_down_sync(0xffffffffu, p.x, 2);
                b4.y = p.y | __shfl_down_sync(0xffffffffu, p.y, 2);
                b4.z = p.z | __shfl_down_sync(0xffffffffu, p.z, 2);
                b4.w = p.w | __shfl_down_sync(0xffffffffu, p.w, 2);
                o.x = b4.x | __shfl_up_sync(0xffffffffu, b4.x, 3);
                o.y = b4.y | __shfl_up_sync(0xffffffffu, b4.y, 3);
                o.z = b4.z | __shfl_up_sync(0xffffffffu, b4.z, 3);
                o.w = b4.w | __shfl_up_sync(0xffffffffu, b4.w, 3);
                grow.x = o.x & gm.x;
                grow.y = o.y & gm.y;
                grow.z = o.z & gm.z;
                grow.w = o.w & gm.w;
                if (l == 15) grow.y |= (1u << 16);
            }
            Gs[rr] = grow;
        }
        __syncthreads();

        // ======== main loop: iterations 4..14 (R12 body, unchanged) ========
        for (int it = 4; it < 15; it++) {
            int R   = 3 * (it + 1);                // 15..45
            int lo  = 48 - R, hi = 48 + R;
            int rlo = lo - 3, rhi = hi + 3;        // within [0,96]
            int jlo = lo >> 3, jhi = hi >> 3;
            int btlo = jlo << 3, bthi = (jhi << 3) + 7;

            // --- horizontal 7-max (half2, 16-output units): A -> Bt ---
            {
                unsigned g = tid / 97u;            // col group (16 cols); 0..6 active
                int y = (int)(tid - g * 97u);
                int X = (int)(g << 4);
                if (g < 7 && y >= rlo && y <= rhi && X <= bthi && X + 15 >= btlo) {
                    const uint4* src = (const uint4*)(A + y * PH + X);  // cols X-8..X+23
                    uint4 t0 = src[0], t1 = src[1], t2 = src[2], t3 = src[3];
                    unsigned v[16] = {t0.x, t0.y, t0.z, t0.w, t1.x, t1.y, t1.z, t1.w,
                                      t2.x, t2.y, t2.z, t2.w, t3.x, t3.y, t3.z, t3.w};
                    unsigned a2[13];
                    #pragma unroll
                    for (int j2 = 0; j2 < 13; j2++)
                        a2[j2] = hmax2u(v[j2], FSR(v[j2], v[j2 + 1]));
                    unsigned q4[12];
                    #pragma unroll
                    for (int j2 = 0; j2 < 12; j2++)
                        q4[j2] = hmax2u(a2[j2], a2[j2 + 1]);
                    unsigned o[8];
                    #pragma unroll
                    for (int m2 = 0; m2 < 8; m2++)
                        o[m2] = hmax2u(FSR(q4[m2 + 2], q4[m2 + 3]), q4[m2 + 4]);
                    uint4* dst = (uint4*)(Bt + y * PH + PADC + X);
                    dst[0] = make_uint4(o[0], o[1], o[2], o[3]);
                    dst[1] = make_uint4(o[4], o[5], o[6], o[7]);
                }
            }
            // --- gt bitwise horizontal dilate ---
            if (tid >= 927) {
                int gy2 = tid - 927;
                uint4 x = Gs[gy2];
                uint4 d = bor(x, bor(bshl(x, 1), bshr(x, 1)));
                d = bor(d, bor(bshl(x, 2), bshr(x, 2)));
                d = bor(d, bor(bshl(x, 3), bshr(x, 3)));
                Gh[gy2] = d;
            }
            __syncthreads();

            // --- vertical 7-max (3-row bands, 8-col groups) + min(mask) + seed ---
            {
                unsigned j = tid % 13u;
                unsigned band = tid / 13u;
                int y0 = lo + (int)band * 3;
                if ((int)j >= jlo && (int)j <= jhi && y0 <= hi) {
                    int hoff = PADC + ((int)j << 3);
                    uint4 t = *(const uint4*)(Bt + (y0 - 1) * PH + hoff);
                    #pragma unroll
                    for (int i = 0; i < 4; i++)
                        t = h8max(t, *(const uint4*)(Bt + (y0 + i) * PH + hoff));
                    uint4 rA = *(const uint4*)(Bt + (y0 - 3) * PH + hoff);
                    uint4 rB = *(const uint4*)(Bt + (y0 - 2) * PH + hoff);
                    int r4 = y0 + 4 > rhi ? rhi : y0 + 4;
                    int r5 = y0 + 5 > rhi ? rhi : y0 + 5;
                    uint4 rC = *(const uint4*)(Bt + r4 * PH + hoff);
                    uint4 rD = *(const uint4*)(Bt + r5 * PH + hoff);
                    uint4 m0 = h8max(t, h8max(rA, rB));
                    uint4 m1 = h8max(t, h8max(rB, rC));
                    uint4 m2 = h8max(t, h8max(rC, rD));
                    uint4 val0 = h8min(m0, *(const uint4*)(M + y0 * PH + hoff));
                    if (y0 == 48 && j == 6u) val0.x = hmax2u(val0.x, seedlo);
                    *(uint4*)(A + y0 * PH + hoff) = val0;
                    if (y0 + 1 <= hi) {
                        uint4 val1 = h8min(m1, *(const uint4*)(M + (y0 + 1) * PH + hoff));
                        if (y0 + 1 == 48 && j == 6u) val1.x = hmax2u(val1.x, seedlo);
                        *(uint4*)(A + (y0 + 1) * PH + hoff) = val1;
                    }
                    if (y0 + 2 <= hi) {
                        uint4 val2 = h8min(m2, *(const uint4*)(M + (y0 + 2) * PH + hoff));
                        if (y0 + 2 == 48 && j == 6u) val2.x = hmax2u(val2.x, seedlo);
                        *(uint4*)(A + (y0 + 2) * PH + hoff) = val2;
                    }
                }
            }
            // --- gt bitwise vertical dilate + AND mask + seed ---
            if (tid >= 927) {
                int y = tid - 927;
                int ym3 = y - 3 < 0 ? 0 : y - 3;
                int yp3 = y + 3 > 96 ? 96 : y + 3;
                uint4 acc = Gh[ym3];
                for (int yy = ym3 + 1; yy <= yp3; yy++) acc = bor(acc, Gh[yy]);
                acc.x &= Gm[y].x; acc.y &= Gm[y].y; acc.z &= Gm[y].z; acc.w &= Gm[y].w;
                if (y == 48 && sv > 0.f) acc.y |= (1u << 16);
                Gs[y] = acc;
            }
            __syncthreads();
        }

        // ---- fused BCE: mantissa-product + exponent accumulation ----
        int ylo = 3 > -gr0 ? 3 : -gr0;
        int yhi = 93 < 255 - gr0 ? 93 : 255 - gr0;
        int xlo = 3 > -gc0 ? 3 : -gc0;
        int xhi = 93 < 255 - gc0 ? 93 : 255 - gc0;
        int nrows2 = yhi - ylo + 1;
        float pm = 1.0f;
        int   pe = 0;
        for (unsigned u = tid; u < (unsigned)nrows2 * 13u; u += 1024) {
            unsigned yy = u / 13u;
            unsigned g = u - yy * 13u;
            int y = ylo + (int)yy;
            int C = (int)(g << 3);
            if (C + 7 < xlo || C > xhi) continue;
            uint4 pv8 = *(const uint4*)(A + y * PH + PADC + C);
            uint4 gw = Gs[y];
            float2 f[4];
            f[0] = __half22float2(*(__half2*)&pv8.x);
            f[1] = __half22float2(*(__half2*)&pv8.y);
            f[2] = __half22float2(*(__half2*)&pv8.z);
            f[3] = __half22float2(*(__half2*)&pv8.w);
            const float* fv = (const float*)f;
            #pragma unroll
            for (int k = 0; k < 8; k++) {
                int x = C + k;
                if (x >= xlo && x <= xhi) {
                    float p = fminf(fmaxf(fv[k], 1e-7f), 1.0f - 1e-7f);
                    int ws = x >> 5;
                    unsigned word = ws == 0 ? gw.x : ws == 1 ? gw.y : ws == 2 ? gw.z : gw.w;
                    float t = ((word >> (x & 31)) & 1u) ? p : (1.0f - p);
                    pm *= t;
                }
                if ((k & 3) == 3) {
                    int bi = __float_as_int(pm);
                    pe += (bi >> 23) - 127;
                    pm = __int_as_float((bi & 0x007fffff) | 0x3f800000);
                }
            }
        }
        float local = -(__logf(pm) + (float)pe * 0.69314718056f);

        #pragma unroll
        for (int off = 16; off; off >>= 1)
            local += __shfl_down_sync(0xffffffffu, local, off);
        if ((tid & 31) == 0) wpart[tid >> 5] = local;
        __syncthreads();
        if (tid == 0) {
            float s = 0.f;
            #pragma unroll
            for (int k = 0; k < 32; k++) s += wpart[k];
            float area = (float)((yhi - ylo + 1) * (xhi - xlo + 1));
            s += (65536.0f - area) * c0log;
            g_partial[ch] = s;
        }
    }

    // ---- last-block finalize ----
    if (tid == 0) {
        __threadfence();
        int old = atomicAdd(&g_done, 1);
        s_last = (old == NCH - 1);
    }
    __syncthreads();
    if (s_last && tid < 32) {
        float v = g_partial[tid] + g_partial[tid + 32] +
                  g_partial[tid + 64] + g_partial[tid + 96];
        #pragma unroll
        for (int off = 16; off; off >>= 1)
            v += __shfl_down_sync(0xffffffffu, v, off);
        if (tid == 0) {
            out[0] = 0.5f * v / 8388608.0f;
            g_done = 0;
        }
    }
}

extern "C" void kernel_launch(void* const* d_in, const int* in_sizes, int n_in,
                              void* d_out, int out_size) {
    const float* cls = (const float*)d_in[0];
    const int* lab   = (const int*)d_in[1];
    const float4* seeds = (const float4*)d_in[2];

    cudaFuncSetAttribute(k_flood, cudaFuncAttributeMaxDynamicSharedMemorySize, SMEM_BYTES);

    k_prep<<<2048, 256>>>(cls, lab, seeds);

    cudaLaunchConfig_t cfg = {};
    cfg.gridDim = dim3(128, 1, 1);
    cfg.blockDim = dim3(1024, 1, 1);
    cfg.dynamicSmemBytes = SMEM_BYTES;
    cfg.stream = 0;
    cudaLaunchAttribute attr[1];
    attr[0].id = cudaLaunchAttributeProgrammaticStreamSerialization;
    attr[0].val.programmaticStreamSerializationAllowed = 1;
    cfg.attrs = attr;
    cfg.numAttrs = 1;
    float* outp = (float*)d_out;
    cudaError_t e = cudaLaunchKernelEx(&cfg, k_flood, outp);
    if (e != cudaSuccess) {
        k_flood<<<128, 1024, SMEM_BYTES>>>(outp);
    }
}

// round 17
// speedup vs baseline: 1.4917x; 1.0255x over previous
#include <cuda_runtime.h>
#include <cuda_fp16.h>
#include <math.h>

// B=4, C=2, H=W=1024, DS=4 -> 256x256, NUM_SEEDS=32, 15 steps, pool 7x7.
#define NCH   128
#define RS    97
#define PH    136             // halfs per row (272B) -> conflict-free LDS.128
#define PADC  8
#define ARRH  (RS * PH + 16)
#define SMEM_BYTES (3 * ARRH * 2)

__device__ float    g_road[4 * 256 * 256];
__device__ unsigned g_gtb[4 * 256 * 8];
__device__ int   g_sr[NCH];
__device__ int   g_sc[NCH];
__device__ int   g_scnt[NCH];
__device__ float g_sv[NCH];
__device__ float g_partial[NCH];
__device__ int   g_done;

__global__ void k_prep(const float* __restrict__ cls, const int* __restrict__ lab,
                       const float4* __restrict__ seeds) {
    if (blockIdx.x < 1024) {
        int idx = blockIdx.x * 256 + threadIdx.x;
        int j = idx & 255, i = (idx >> 8) & 255, b = idx >> 16;
        const float* c0 = cls + (size_t)(b * 2 + 0) * 1048576;
        const float* c1 = cls + (size_t)(b * 2 + 1) * 1048576;
        int r1 = 4 * i + 1, r2 = 4 * i + 2, cc = 4 * j;
        float4 a0 = *(const float4*)(c0 + r1 * 1024 + cc);
        float4 a1 = *(const float4*)(c1 + r1 * 1024 + cc);
        float4 b0 = *(const float4*)(c0 + r2 * 1024 + cc);
        float4 b1 = *(const float4*)(c1 + r2 * 1024 + cc);
        float p1 = 1.f / (1.f + expf(a0.y - a1.y));
        float p2 = 1.f / (1.f + expf(a0.z - a1.z));
        float p3 = 1.f / (1.f + expf(b0.y - b1.y));
        float p4 = 1.f / (1.f + expf(b0.z - b1.z));
        g_road[idx] = 0.25f * (p1 + p2 + p3 + p4);
        int g = lab[((size_t)b * 1024 + 4 * i) * 1024 + 4 * j];
        unsigned bits = __ballot_sync(0xffffffffu, g != 0);
        if ((threadIdx.x & 31) == 0)
            g_gtb[((size_t)b * 256 + i) * 8 + (j >> 5)] = bits;
    }
    {
        const unsigned n4 = (4 * 32 * 256 * 256) / 4;
        for (unsigned i = blockIdx.x * 256u + threadIdx.x; i < n4; i += 2048u * 256u) {
            float4 v = seeds[i];
            if (v.x > 0.f || v.y > 0.f || v.z > 0.f || v.w > 0.f) {
                float vals[4] = {v.x, v.y, v.z, v.w};
                #pragma unroll
                for (int k = 0; k < 4; k++) if (vals[k] > 0.f) {
                    unsigned idx = i * 4u + k;
                    int ch = idx >> 16;
                    g_sr[ch] = (idx >> 8) & 255;
                    g_sc[ch] = idx & 255;
                    g_sv[ch] = vals[k];
                    g_scnt[ch] = 1;
                }
            }
        }
    }
    asm volatile("griddepcontrol.launch_dependents;" ::: "memory");
}

__device__ __forceinline__ unsigned getword(const unsigned* row, int start) {
    int w = start >> 5;
    int sh = start & 31;
    unsigned lo = ((unsigned)w < 8u) ? row[w] : 0u;
    unsigned hi = ((unsigned)(w + 1) < 8u) ? row[w + 1] : 0u;
    return __funnelshift_r(lo, hi, sh);
}
__device__ __forceinline__ uint4 bshl(uint4 v, int s) {
    return make_uint4(v.x << s, __funnelshift_l(v.x, v.y, s),
                      __funnelshift_l(v.y, v.z, s), __funnelshift_l(v.z, v.w, s));
}
__device__ __forceinline__ uint4 bshr(uint4 v, int s) {
    return make_uint4(__funnelshift_r(v.x, v.y, s), __funnelshift_r(v.y, v.z, s),
                      __funnelshift_r(v.z, v.w, s), v.w >> s);
}
__device__ __forceinline__ uint4 bor(uint4 a, uint4 b) {
    return make_uint4(a.x | b.x, a.y | b.y, a.z | b.z, a.w | b.w);
}
__device__ __forceinline__ unsigned hmax2u(unsigned a, unsigned b) {
    __half2 r = __hmax2(*(__half2*)&a, *(__half2*)&b);
    return *(unsigned*)&r;
}
__device__ __forceinline__ unsigned hmin2u(unsigned a, unsigned b) {
    __half2 r = __hmin2(*(__half2*)&a, *(__half2*)&b);
    return *(unsigned*)&r;
}
__device__ __forceinline__ uint4 h8max(uint4 a, uint4 b) {
    return make_uint4(hmax2u(a.x, b.x), hmax2u(a.y, b.y),
                      hmax2u(a.z, b.z), hmax2u(a.w, b.w));
}
__device__ __forceinline__ uint4 h8min(uint4 a, uint4 b) {
    return make_uint4(hmin2u(a.x, b.x), hmin2u(a.y, b.y),
                      hmin2u(a.z, b.z), hmin2u(a.w, b.w));
}
#define FSR(a, b) __funnelshift_r((a), (b), 16)

// One channel per CTA, 1024 threads, 128 CTAs (full chip).
__global__ void __launch_bounds__(1024, 1) k_flood(float* __restrict__ out) {
    extern __shared__ __half smh[];
    __half* A  = smh;
    __half* Bt = smh + ARRH;
    __half* M  = smh + 2 * ARRH;
    __shared__ uint4 Gs[RS];
    __shared__ uint4 Gh[RS];
    __shared__ uint4 Gm[RS];
    __shared__ float wpart[32];
    __shared__ int   s_last;

    unsigned tid = threadIdx.x;
    int ch  = blockIdx.x;
    int b   = ch >> 5;
    const float c0log = -logf(1.0f - 1e-7f);

    // ---- pre-dependency: zero A and M while k_prep finishes (PDL overlap) ----
    {
        uint4 z = make_uint4(0, 0, 0, 0);
        uint4* A8 = (uint4*)A;
        uint4* M8 = (uint4*)M;
        for (int i = tid; i < ARRH / 8; i += 1024) { A8[i] = z; M8[i] = z; }
    }
    asm volatile("griddepcontrol.wait;" ::: "memory");
    __syncthreads();

    bool hasseed = (g_scnt[ch] != 0);
    if (!hasseed) {
        if (tid == 0) g_partial[ch] = 65536.0f * c0log;
    } else {
        int sr = g_sr[ch], sc = g_sc[ch];
        float sv = g_sv[ch];
        int gr0 = sr - 48, gc0 = sc - 48;

        if (tid >= 927) {
            int gy2 = tid - 927;               // 0..96
            int gy = gr0 + gy2;
            uint4 gm = make_uint4(0, 0, 0, 0);
            if ((unsigned)gy < 256u) {
                const unsigned* row = &g_gtb[((size_t)b * 256 + gy) * 8];
                gm.x = getword(row, gc0);
                gm.y = getword(row, gc0 + 32);
                gm.z = getword(row, gc0 + 64);
                gm.w = getword(row, gc0 + 96);
            }
            gm.w &= 1u;
            Gm[gy2] = gm;
            Gs[gy2] = make_uint4(0, 0, 0, 0);
        }
        for (unsigned idx = tid; idx < RS * RS; idx += 1024) {
            unsigned y = idx / RS;
            unsigned x = idx - y * RS;
            int gy = gr0 + (int)y, gx = gc0 + (int)x;
            float m = 0.f;
            if ((unsigned)gy < 256u && (unsigned)gx < 256u)
                m = g_road[(b << 16) + (gy << 8) + gx];
            M[y * PH + PADC + x] = __float2half(m);
        }
        __syncthreads();

        unsigned seedlo = (unsigned)__half_as_ushort(__float2half(sv));
        int w = tid >> 5, l = tid & 31;

        // ======== warp-local fast path: iterations 0..4 (radius <= 15) ========
        if (w == 0) {
            // float field: lane = row 33+l, regs v[0..15] = cols 32..63
            int rr = 33 + l;
            const unsigned* mrow = (const unsigned*)(M + rr * PH + PADC + 32);
            unsigned v[16];
            #pragma unroll
            for (int k = 0; k < 16; k++) v[k] = 0u;
            if (l == 15) v[8] = seedlo;          // row 48, col 48 (lo half)
            #pragma unroll
            for (int it2 = 0; it2 < 5; it2++) {
                unsigned a[17], bb[16], h[16];
                a[16] = 0u;
                #pragma unroll
                for (int k = 0; k < 16; k++) {
                    unsigned nx = (k + 1 < 16) ? v[k + 1] : 0u;
                    a[k] = hmax2u(v[k], FSR(v[k], nx));
                }
                #pragma unroll
                for (int k = 0; k < 16; k++)
                    bb[k] = hmax2u(a[k], a[k + 1]);
                // h[j] for all 16 regs; virtual bb[-1] = bb[-2] = 0 (cols 28..31 zero)
                h[0] = bb[0];
                h[1] = hmax2u(FSR(0u, bb[0]), bb[1]);
                #pragma unroll
                for (int k = 2; k < 16; k++)
                    h[k] = hmax2u(FSR(bb[k - 2], bb[k - 1]), bb[k]);
                #pragma unroll
                for (int k = 0; k < 16; k++) {
                    unsigned p  = hmax2u(h[k], __shfl_down_sync(0xffffffffu, h[k], 1));
                    unsigned b4 = hmax2u(p,   __shfl_down_sync(0xffffffffu, p, 2));
                    unsigned o  = hmax2u(b4,  __shfl_up_sync(0xffffffffu, b4, 3));
                    v[k] = hmin2u(o, mrow[k]);
                }
                if (l == 15) v[8] = hmax2u(v[8], seedlo);
            }
            uint4* dst = (uint4*)(A + rr * PH + PADC + 32);
            dst[0] = make_uint4(v[0],  v[1],  v[2],  v[3]);
            dst[1] = make_uint4(v[4],  v[5],  v[6],  v[7]);
            dst[2] = make_uint4(v[8],  v[9],  v[10], v[11]);
            dst[3] = make_uint4(v[12], v[13], v[14], v[15]);
        } else if (w == 1) {
            // gt bit field: lane = row 33+l, full-row uint4
            int rr = 33 + l;
            uint4 gm = Gm[rr];
            uint4 grow = make_uint4(0, 0, 0, 0);
            if (l == 15) grow.y |= (1u << 16);
            #pragma unroll
            for (int it2 = 0; it2 < 5; it2++) {
                uint4 gh = bor(grow, bor(bshl(grow, 1), bshr(grow, 1)));
                gh = bor(gh, bor(bshl(grow, 2), bshr(grow, 2)));
                gh = bor(gh, bor(bshl(grow, 3), bshr(grow, 3)));
                uint4 p, b4, o;
                p.x = gh.x | __shfl_down_sync(0xffffffffu, gh.x, 1);
                p.y = gh.y | __shfl_down_sync(0xffffffffu, gh.y, 1);
                p.z = gh.z | __shfl_down_sync(0xffffffffu, gh.z, 1);
                p.w = gh.w | __shfl_down_sync(0xffffffffu, gh.w, 1);
                b4.x = p.x | __shfl_down_sync(0xffffffffu, p.x, 2);
                b4.y = p.y | __shfl_down_sync(0xffffffffu, p.y, 2);
                b4.z = p.z | __shfl_down_sync(0xffffffffu, p.z, 2);
                b4.w = p.w | __shfl_down_sync(0xffffffffu, p.w, 2);
                o.x = b4.x | __shfl_up_sync(0xffffffffu, b4.x, 3);
                o.y = b4.y | __shfl_up_sync(0xffffffffu, b4.y, 3);
                o.z = b4.z | __shfl_up_sync(0xffffffffu, b4.z, 3);
                o.w = b4.w | __shfl_up_sync(0xffffffffu, b4.w, 3);
                grow.x = o.x & gm.x;
                grow.y = o.y & gm.y;
                grow.z = o.z & gm.z;
                grow.w = o.w & gm.w;
                if (l == 15) grow.y |= (1u << 16);
            }
            Gs[rr] = grow;
        }
        __syncthreads();

        // ======== main loop: iterations 5..14 (R12 body, unchanged) ========
        for (int it = 5; it < 15; it++) {
            int R   = 3 * (it + 1);                // 18..45
            int lo  = 48 - R, hi = 48 + R;
            int rlo = lo - 3, rhi = hi + 3;        // within [0,96]
            int jlo = lo >> 3, jhi = hi >> 3;
            int btlo = jlo << 3, bthi = (jhi << 3) + 7;

            // --- horizontal 7-max (half2, 16-output units): A -> Bt ---
            {
                unsigned g = tid / 97u;            // col group (16 cols); 0..6 active
                int y = (int)(tid - g * 97u);
                int X = (int)(g << 4);
                if (g < 7 && y >= rlo && y <= rhi && X <= bthi && X + 15 >= btlo) {
                    const uint4* src = (const uint4*)(A + y * PH + X);  // cols X-8..X+23
                    uint4 t0 = src[0], t1 = src[1], t2 = src[2], t3 = src[3];
                    unsigned v[16] = {t0.x, t0.y, t0.z, t0.w, t1.x, t1.y, t1.z, t1.w,
                                      t2.x, t2.y, t2.z, t2.w, t3.x, t3.y, t3.z, t3.w};
                    unsigned a2[13];
                    #pragma unroll
                    for (int j2 = 0; j2 < 13; j2++)
                        a2[j2] = hmax2u(v[j2], FSR(v[j2], v[j2 + 1]));
                    unsigned q4[12];
                    #pragma unroll
                    for (int j2 = 0; j2 < 12; j2++)
                        q4[j2] = hmax2u(a2[j2], a2[j2 + 1]);
                    unsigned o[8];
                    #pragma unroll
                    for (int m2 = 0; m2 < 8; m2++)
                        o[m2] = hmax2u(FSR(q4[m2 + 2], q4[m2 + 3]), q4[m2 + 4]);
                    uint4* dst = (uint4*)(Bt + y * PH + PADC + X);
                    dst[0] = make_uint4(o[0], o[1], o[2], o[3]);
                    dst[1] = make_uint4(o[4], o[5], o[6], o[7]);
                }
            }
            // --- gt bitwise horizontal dilate ---
            if (tid >= 927) {
                int gy2 = tid - 927;
                uint4 x = Gs[gy2];
                uint4 d = bor(x, bor(bshl(x, 1), bshr(x, 1)));
                d = bor(d, bor(bshl(x, 2), bshr(x, 2)));
                d = bor(d, bor(bshl(x, 3), bshr(x, 3)));
                Gh[gy2] = d;
            }
            __syncthreads();

            // --- vertical 7-max (3-row bands, 8-col groups) + min(mask) + seed ---
            {
                unsigned j = tid % 13u;
                unsigned band = tid / 13u;
                int y0 = lo + (int)band * 3;
                if ((int)j >= jlo && (int)j <= jhi && y0 <= hi) {
                    int hoff = PADC + ((int)j << 3);
                    uint4 t = *(const uint4*)(Bt + (y0 - 1) * PH + hoff);
                    #pragma unroll
                    for (int i = 0; i < 4; i++)
                        t = h8max(t, *(const uint4*)(Bt + (y0 + i) * PH + hoff));
                    uint4 rA = *(const uint4*)(Bt + (y0 - 3) * PH + hoff);
                    uint4 rB = *(const uint4*)(Bt + (y0 - 2) * PH + hoff);
                    int r4 = y0 + 4 > rhi ? rhi : y0 + 4;
                    int r5 = y0 + 5 > rhi ? rhi : y0 + 5;
                    uint4 rC = *(const uint4*)(Bt + r4 * PH + hoff);
                    uint4 rD = *(const uint4*)(Bt + r5 * PH + hoff);
                    uint4 m0 = h8max(t, h8max(rA, rB));
                    uint4 m1 = h8max(t, h8max(rB, rC));
                    uint4 m2 = h8max(t, h8max(rC, rD));
                    uint4 val0 = h8min(m0, *(const uint4*)(M + y0 * PH + hoff));
                    if (y0 == 48 && j == 6u) val0.x = hmax2u(val0.x, seedlo);
                    *(uint4*)(A + y0 * PH + hoff) = val0;
                    if (y0 + 1 <= hi) {
                        uint4 val1 = h8min(m1, *(const uint4*)(M + (y0 + 1) * PH + hoff));
                        if (y0 + 1 == 48 && j == 6u) val1.x = hmax2u(val1.x, seedlo);
                        *(uint4*)(A + (y0 + 1) * PH + hoff) = val1;
                    }
                    if (y0 + 2 <= hi) {
                        uint4 val2 = h8min(m2, *(const uint4*)(M + (y0 + 2) * PH + hoff));
                        if (y0 + 2 == 48 && j == 6u) val2.x = hmax2u(val2.x, seedlo);
                        *(uint4*)(A + (y0 + 2) * PH + hoff) = val2;
                    }
                }
            }
            // --- gt bitwise vertical dilate + AND mask + seed ---
            if (tid >= 927) {
                int y = tid - 927;
                int ym3 = y - 3 < 0 ? 0 : y - 3;
                int yp3 = y + 3 > 96 ? 96 : y + 3;
                uint4 acc = Gh[ym3];
                for (int yy = ym3 + 1; yy <= yp3; yy++) acc = bor(acc, Gh[yy]);
                acc.x &= Gm[y].x; acc.y &= Gm[y].y; acc.z &= Gm[y].z; acc.w &= Gm[y].w;
                if (y == 48 && sv > 0.f) acc.y |= (1u << 16);
                Gs[y] = acc;
            }
            __syncthreads();
        }

        // ---- fused BCE: mantissa-product + exponent accumulation ----
        int ylo = 3 > -gr0 ? 3 : -gr0;
        int yhi = 93 < 255 - gr0 ? 93 : 255 - gr0;
        int xlo = 3 > -gc0 ? 3 : -gc0;
        int xhi = 93 < 255 - gc0 ? 93 : 255 - gc0;
        int nrows2 = yhi - ylo + 1;
        float pm = 1.0f;
        int   pe = 0;
        for (unsigned u = tid; u < (unsigned)nrows2 * 13u; u += 1024) {
            unsigned yy = u / 13u;
            unsigned g = u - yy * 13u;
            int y = ylo + (int)yy;
            int C = (int)(g << 3);
            if (C + 7 < xlo || C > xhi) continue;
            uint4 pv8 = *(const uint4*)(A + y * PH + PADC + C);
            uint4 gw = Gs[y];
            float2 f[4];
            f[0] = __half22float2(*(__half2*)&pv8.x);
            f[1] = __half22float2(*(__half2*)&pv8.y);
            f[2] = __half22float2(*(__half2*)&pv8.z);
            f[3] = __half22float2(*(__half2*)&pv8.w);
            const float* fv = (const float*)f;
            #pragma unroll
            for (int k = 0; k < 8; k++) {
                int x = C + k;
                if (x >= xlo && x <= xhi) {
                    float p = fminf(fmaxf(fv[k], 1e-7f), 1.0f - 1e-7f);
                    int ws = x >> 5;
                    unsigned word = ws == 0 ? gw.x : ws == 1 ? gw.y : ws == 2 ? gw.z : gw.w;
                    float t = ((word >> (x & 31)) & 1u) ? p : (1.0f - p);
                    pm *= t;
                }
                if ((k & 3) == 3) {
                    int bi = __float_as_int(pm);
                    pe += (bi >> 23) - 127;
                    pm = __int_as_float((bi & 0x007fffff) | 0x3f800000);
                }
            }
        }
        float local = -(__logf(pm) + (float)pe * 0.69314718056f);

        #pragma unroll
        for (int off = 16; off; off >>= 1)
            local += __shfl_down_sync(0xffffffffu, local, off);
        if ((tid & 31) == 0) wpart[tid >> 5] = local;
        __syncthreads();
        if (tid == 0) {
            float s = 0.f;
            #pragma unroll
            for (int k = 0; k < 32; k++) s += wpart[k];
            float area = (float)((yhi - ylo + 1) * (xhi - xlo + 1));
            s += (65536.0f - area) * c0log;
            g_partial[ch] = s;
        }
    }

    // ---- last-block finalize ----
    if (tid == 0) {
        __threadfence();
        int old = atomicAdd(&g_done, 1);
        s_last = (old == NCH - 1);
    }
    __syncthreads();
    if (s_last && tid < 32) {
        float v = g_partial[tid] + g_partial[tid + 32] +
                  g_partial[tid + 64] + g_partial[tid + 96];
        #pragma unroll
        for (int off = 16; off; off >>= 1)
            v += __shfl_down_sync(0xffffffffu, v, off);
        if (tid == 0) {
            out[0] = 0.5f * v / 8388608.0f;
            g_done = 0;
        }
    }
}

extern "C" void kernel_launch(void* const* d_in, const int* in_sizes, int n_in,
                              void* d_out, int out_size) {
    const float* cls = (const float*)d_in[0];
    const int* lab   = (const int*)d_in[1];
    const float4* seeds = (const float4*)d_in[2];

    cudaFuncSetAttribute(k_flood, cudaFuncAttributeMaxDynamicSharedMemorySize, SMEM_BYTES);

    k_prep<<<2048, 256>>>(cls, lab, seeds);

    cudaLaunchConfig_t cfg = {};
    cfg.gridDim = dim3(128, 1, 1);
    cfg.blockDim = dim3(1024, 1, 1);
    cfg.dynamicSmemBytes = SMEM_BYTES;
    cfg.stream = 0;
    cudaLaunchAttribute attr[1];
    attr[0].id = cudaLaunchAttributeProgrammaticStreamSerialization;
    attr[0].val.programmaticStreamSerializationAllowed = 1;
    cfg.attrs = attr;
    cfg.numAttrs = 1;
    float* outp = (float*)d_out;
    cudaError_t e = cudaLaunchKernelEx(&cfg, k_flood, outp);
    if (e != cudaSuccess) {
        k_flood<<<128, 1024, SMEM_BYTES>>>(outp);
    }
}